// round 4
// baseline (speedup 1.0000x reference)
#include <cuda_runtime.h>
#include <math.h>

#define B_ 8
#define T_ 2048
#define H_ 64
#define M_ 32
#define S_ 20
#define E_ 3
#define IN_ 32
#define EPS_ 1e-8f

// Scratch (allocation-free rule: __device__ globals)
__device__ float g_mem[B_*T_*M_];       // memories [B,T,M]
__device__ float g_Q[E_*B_*T_*M_];
__device__ float g_K[E_*B_*T_*M_];
__device__ float g_V[E_*B_*T_*M_];

__device__ __forceinline__ float warpSum(float v){
  #pragma unroll
  for (int o=16;o>0;o>>=1) v += __shfl_xor_sync(0xffffffffu, v, o);
  return v;
}
__device__ __forceinline__ float warpMax(float v){
  #pragma unroll
  for (int o=16;o>0;o>>=1) v = fmaxf(v, __shfl_xor_sync(0xffffffffu, v, o));
  return v;
}

// ---------------------------------------------------------------------------
// Kernel 1: memories = softmax(x@IQ @ memory^T) @ memory   per (b,t)
// 1 warp per (b,t); lane = m index.
// ---------------------------------------------------------------------------
__global__ void mem_kernel(const float* __restrict__ x,
                           const float* __restrict__ memory,
                           const float* __restrict__ iq)
{
  __shared__ float IQs[IN_*M_];
  __shared__ float MEMs[S_*M_];
  int tid = threadIdx.x;
  for (int i = tid; i < IN_*M_; i += 128) IQs[i]  = iq[i];
  for (int i = tid; i < S_*M_;  i += 128) MEMs[i] = memory[i];
  __syncthreads();

  int warp = tid >> 5, lane = tid & 31;
  int bt = blockIdx.x*4 + warp;

  float xv = x[bt*IN_ + lane];
  float q = 0.f;
  #pragma unroll
  for (int i = 0; i < IN_; i++)
    q += __shfl_sync(0xffffffffu, xv, i) * IQs[i*M_ + lane];

  float sc[S_];
  float mx = -INFINITY;
  #pragma unroll
  for (int s = 0; s < S_; s++){
    float v = warpSum(q * MEMs[s*M_ + lane]);
    sc[s] = v; mx = fmaxf(mx, v);
  }
  float sum = 0.f;
  #pragma unroll
  for (int s = 0; s < S_; s++){ sc[s] = __expf(sc[s]-mx); sum += sc[s]; }
  float m = 0.f;
  #pragma unroll
  for (int s = 0; s < S_; s++) m += sc[s]*MEMs[s*M_ + lane];
  g_mem[bt*M_ + lane] = m / sum;
}

// ---------------------------------------------------------------------------
// Kernel 2: Q/K/V = hidden @ Wq/Wk/Wv per expert.  W tiles in smem,
// hidden row distributed across lanes + shfl broadcast. lane = m.
// ---------------------------------------------------------------------------
__global__ __launch_bounds__(256) void qkv_kernel(const float* __restrict__ hidden,
                           const float* __restrict__ Wq,
                           const float* __restrict__ Wk,
                           const float* __restrict__ Wv)
{
  __shared__ float Wqs[H_*M_], Wks[H_*M_], Wvs[H_*M_];
  int e = blockIdx.y;
  int tid = threadIdx.x;
  for (int i = tid; i < H_*M_; i += 256){
    Wqs[i] = Wq[e*H_*M_ + i];
    Wks[i] = Wk[e*H_*M_ + i];
    Wvs[i] = Wv[e*H_*M_ + i];
  }
  __syncthreads();

  int warp = tid >> 5, lane = tid & 31;
  int rowBase = blockIdx.x*64 + warp*8;
  #pragma unroll
  for (int rr = 0; rr < 8; rr++){
    int row = rowBase + rr;
    long gr = (long)e*B_*T_ + row;
    float h0 = hidden[gr*H_ + lane];
    float h1 = hidden[gr*H_ + 32 + lane];
    float q = 0.f, k = 0.f, v = 0.f;
    #pragma unroll
    for (int h = 0; h < 32; h++){
      float hv = __shfl_sync(0xffffffffu, h0, h);
      q += hv*Wqs[h*M_+lane]; k += hv*Wks[h*M_+lane]; v += hv*Wvs[h*M_+lane];
    }
    #pragma unroll
    for (int h = 0; h < 32; h++){
      float hv = __shfl_sync(0xffffffffu, h1, h);
      q += hv*Wqs[(h+32)*M_+lane]; k += hv*Wks[(h+32)*M_+lane]; v += hv*Wvs[(h+32)*M_+lane];
    }
    g_Q[gr*M_+lane] = q; g_K[gr*M_+lane] = k; g_V[gr*M_+lane] = v;
  }
}

// ---------------------------------------------------------------------------
// Kernel 3: flash attention (online softmax) + cosine epilogue.
// Block = 64-query tile for one (e,b). 8 warps; warp owns 8 query rows.
// Key tiles of 32; lane = key index in pass 1, lane = m in pass 2.
// smem rows padded to 36 floats: 16B-aligned AND conflict-free for LDS.128.
// ---------------------------------------------------------------------------
__global__ __launch_bounds__(256) void attn_kernel(float* __restrict__ out)
{
  __shared__ float Qs[64*36];
  __shared__ float Ks[32*36];
  __shared__ float Vs[32*36];
  __shared__ float Psh[8*8*32];

  int tid = threadIdx.x, warp = tid >> 5, lane = tid & 31;
  int eb = blockIdx.y, e = eb >> 3, b = eb & 7;
  const float* Qg = g_Q + (size_t)eb*T_*M_;
  const float* Kg = g_K + (size_t)eb*T_*M_;
  const float* Vg = g_V + (size_t)eb*T_*M_;
  int qbase = blockIdx.x*64;

  for (int i = tid; i < 64*32; i += 256){
    int r = i >> 5, m = i & 31;
    Qs[r*36 + m] = Qg[(qbase + r)*32 + m];
  }

  float acc[8], mx[8], l[8];
  #pragma unroll
  for (int r = 0; r < 8; r++){ acc[r] = 0.f; mx[r] = -INFINITY; l[r] = 0.f; }

  for (int kt = 0; kt < T_/32; kt++){
    __syncthreads();   // protect Ks/Vs reads of previous iter (and Qs fill at kt=0)
    for (int i = tid; i < 32*32; i += 256){
      int r = i >> 5, m = i & 31;
      Ks[r*36 + m] = Kg[(kt*32 + r)*32 + m];
      Vs[r*36 + m] = Vg[(kt*32 + r)*32 + m];
    }
    __syncthreads();

    // pass 1: scores + online softmax.  lane = key k. K row cached in regs.
    float4 kr[8];
    #pragma unroll
    for (int j = 0; j < 8; j++)
      kr[j] = *reinterpret_cast<const float4*>(&Ks[lane*36 + j*4]);

    #pragma unroll
    for (int r = 0; r < 8; r++){
      const float4* qrow = reinterpret_cast<const float4*>(&Qs[(warp*8 + r)*36]);
      float s = 0.f;
      #pragma unroll
      for (int j = 0; j < 8; j++){
        float4 qv = qrow[j];
        s += qv.x*kr[j].x; s += qv.y*kr[j].y;
        s += qv.z*kr[j].z; s += qv.w*kr[j].w;
      }
      float tm   = warpMax(s);
      float nm   = fmaxf(mx[r], tm);
      float p    = __expf(s - nm);
      float corr = __expf(mx[r] - nm);   // exp(-inf)=0 handles first tile
      mx[r] = nm;
      float rs = warpSum(p);
      l[r]   = l[r]*corr + rs;
      acc[r] *= corr;
      Psh[(warp*8 + r)*32 + lane] = p;
    }
    __syncwarp();

    // pass 2: acc += P @ V.  lane = m.  V column cached in regs (reused 8x).
    float vcol[32];
    #pragma unroll
    for (int k = 0; k < 32; k++) vcol[k] = Vs[k*36 + lane];
    #pragma unroll
    for (int r = 0; r < 8; r++){
      const float4* prow = reinterpret_cast<const float4*>(&Psh[(warp*8 + r)*32]);
      float a = acc[r];
      #pragma unroll
      for (int j = 0; j < 8; j++){
        float4 p4 = prow[j];
        a += p4.x*vcol[j*4+0]; a += p4.y*vcol[j*4+1];
        a += p4.z*vcol[j*4+2]; a += p4.w*vcol[j*4+3];
      }
      acc[r] = a;
    }
  }

  // epilogue: out = acc/l ; cos(out, memories[b,t]) with eps-clamped norms
  #pragma unroll
  for (int r = 0; r < 8; r++){
    int t = qbase + warp*8 + r;
    float o  = acc[r] / l[r];
    float mv = g_mem[(b*T_ + t)*32 + lane];
    float dot = warpSum(o*o + 0.0f*mv);       // placeholder removed below
    // compute the three reductions properly:
    dot = warpSum(o*mv);
    float no  = warpSum(o*o);
    float nm2 = warpSum(mv*mv);
    if (lane == 0)
      out[(b*T_ + t)*E_ + e] =
          dot / (fmaxf(sqrtf(no), EPS_) * fmaxf(sqrtf(nm2), EPS_));
  }
}

// ---------------------------------------------------------------------------
extern "C" void kernel_launch(void* const* d_in, const int* in_sizes, int n_in,
                              void* d_out, int out_size)
{
  const float* x      = (const float*)d_in[0];
  const float* hidden = (const float*)d_in[1];
  const float* memory = (const float*)d_in[2];
  const float* Wq     = (const float*)d_in[3];
  const float* Wk     = (const float*)d_in[4];
  const float* Wv     = (const float*)d_in[5];
  const float* iq     = (const float*)d_in[6];
  float* out = (float*)d_out;

  mem_kernel<<<B_*T_/4, 128>>>(x, memory, iq);
  qkv_kernel<<<dim3(B_*T_/64, E_), 256>>>(hidden, Wq, Wk, Wv);
  attn_kernel<<<dim3(T_/64, E_*B_), 256>>>(out);
}

// round 6
// speedup vs baseline: 1.1137x; 1.1137x over previous
#include <cuda_runtime.h>
#include <math.h>

#define B_ 8
#define T_ 2048
#define H_ 64
#define M_ 32
#define S_ 20
#define E_ 3
#define IN_ 32
#define EPS_ 1e-8f
#define THR_ 30.0f   // exp(-30)=9.4e-14; contributions vs l>=1 far below 1e-3 tol

// Scratch (allocation-free rule: __device__ globals)
__device__ float g_mem[B_*T_*M_];       // memories [B,T,M]
__device__ float g_Q[E_*B_*T_*M_];
__device__ float g_K[E_*B_*T_*M_];
__device__ float g_V[E_*B_*T_*M_];

__device__ __forceinline__ float warpSum(float v){
  #pragma unroll
  for (int o=16;o>0;o>>=1) v += __shfl_xor_sync(0xffffffffu, v, o);
  return v;
}
__device__ __forceinline__ float warpMax(float v){
  #pragma unroll
  for (int o=16;o>0;o>>=1) v = fmaxf(v, __shfl_xor_sync(0xffffffffu, v, o));
  return v;
}

// ---------------------------------------------------------------------------
// Kernel 1: memories = softmax(x@IQ @ memory^T) @ memory   per (b,t)
// ---------------------------------------------------------------------------
__global__ void mem_kernel(const float* __restrict__ x,
                           const float* __restrict__ memory,
                           const float* __restrict__ iq)
{
  __shared__ float IQs[IN_*M_];
  __shared__ float MEMs[S_*M_];
  int tid = threadIdx.x;
  for (int i = tid; i < IN_*M_; i += 128) IQs[i]  = iq[i];
  for (int i = tid; i < S_*M_;  i += 128) MEMs[i] = memory[i];
  __syncthreads();

  int warp = tid >> 5, lane = tid & 31;
  int bt = blockIdx.x*4 + warp;

  float xv = x[bt*IN_ + lane];
  float q = 0.f;
  #pragma unroll
  for (int i = 0; i < IN_; i++)
    q += __shfl_sync(0xffffffffu, xv, i) * IQs[i*M_ + lane];

  float sc[S_];
  float mx = -INFINITY;
  #pragma unroll
  for (int s = 0; s < S_; s++){
    float v = warpSum(q * MEMs[s*M_ + lane]);
    sc[s] = v; mx = fmaxf(mx, v);
  }
  float sum = 0.f;
  #pragma unroll
  for (int s = 0; s < S_; s++){ sc[s] = __expf(sc[s]-mx); sum += sc[s]; }
  float m = 0.f;
  #pragma unroll
  for (int s = 0; s < S_; s++) m += sc[s]*MEMs[s*M_ + lane];
  g_mem[bt*M_ + lane] = m / sum;
}

// ---------------------------------------------------------------------------
// Kernel 2: Q/K/V = hidden @ Wq/Wk/Wv per expert.
// ---------------------------------------------------------------------------
__global__ __launch_bounds__(256) void qkv_kernel(const float* __restrict__ hidden,
                           const float* __restrict__ Wq,
                           const float* __restrict__ Wk,
                           const float* __restrict__ Wv)
{
  __shared__ float Wqs[H_*M_], Wks[H_*M_], Wvs[H_*M_];
  int e = blockIdx.y;
  int tid = threadIdx.x;
  for (int i = tid; i < H_*M_; i += 256){
    Wqs[i] = Wq[e*H_*M_ + i];
    Wks[i] = Wk[e*H_*M_ + i];
    Wvs[i] = Wv[e*H_*M_ + i];
  }
  __syncthreads();

  int warp = tid >> 5, lane = tid & 31;
  int rowBase = blockIdx.x*64 + warp*8;
  #pragma unroll
  for (int rr = 0; rr < 8; rr++){
    int row = rowBase + rr;
    long gr = (long)e*B_*T_ + row;
    float h0 = hidden[gr*H_ + lane];
    float h1 = hidden[gr*H_ + 32 + lane];
    float q = 0.f, k = 0.f, v = 0.f;
    #pragma unroll
    for (int h = 0; h < 32; h++){
      float hv = __shfl_sync(0xffffffffu, h0, h);
      q += hv*Wqs[h*M_+lane]; k += hv*Wks[h*M_+lane]; v += hv*Wvs[h*M_+lane];
    }
    #pragma unroll
    for (int h = 0; h < 32; h++){
      float hv = __shfl_sync(0xffffffffu, h1, h);
      q += hv*Wqs[(h+32)*M_+lane]; k += hv*Wks[(h+32)*M_+lane]; v += hv*Wvs[(h+32)*M_+lane];
    }
    g_Q[gr*M_+lane] = q; g_K[gr*M_+lane] = k; g_V[gr*M_+lane] = v;
  }
}

// ---------------------------------------------------------------------------
// Kernel 3: two-pass max-first attention + cosine epilogue.
// Pass 1: exact per-row max over all keys (record per-(row,tile) max).
// Pass 2: exp + PV only on tiles with tmax >= gmax - THR (~1.3 per row).
// Block = 64 query rows of one (e,b); 8 warps x 8 rows; key tiles of 32.
// smem rows padded to 36 floats: 16B-aligned and conflict-free LDS.128.
// ---------------------------------------------------------------------------
__global__ __launch_bounds__(256) void attn_kernel(float* __restrict__ out)
{
  __shared__ float Qs[64*36];
  __shared__ float Ks[32*36];
  __shared__ float Vs[32*36];
  __shared__ float Psh[8*8*32];
  __shared__ float Tmax[64*64];   // [row][tile]

  int tid = threadIdx.x, warp = tid >> 5, lane = tid & 31;
  int eb = blockIdx.y, e = eb >> 3, b = eb & 7;
  const float* Qg = g_Q + (size_t)eb*T_*M_;
  const float* Kg = g_K + (size_t)eb*T_*M_;
  const float* Vg = g_V + (size_t)eb*T_*M_;
  int qbase = blockIdx.x*64;

  for (int i = tid; i < 64*32; i += 256){
    int r = i >> 5, m = i & 31;
    Qs[r*36 + m] = Qg[(qbase + r)*32 + m];
  }

  float mx[8];
  #pragma unroll
  for (int r = 0; r < 8; r++) mx[r] = -INFINITY;

  // ---- pass 1: row max (no exp, no PV) ----
  for (int kt = 0; kt < T_/32; kt++){
    __syncthreads();   // protect Ks reads of prev iter (and Qs fill at kt=0)
    for (int i = tid; i < 32*32; i += 256){
      int r = i >> 5, m = i & 31;
      Ks[r*36 + m] = Kg[(kt*32 + r)*32 + m];
    }
    __syncthreads();

    float4 kr[8];
    #pragma unroll
    for (int j = 0; j < 8; j++)
      kr[j] = *reinterpret_cast<const float4*>(&Ks[lane*36 + j*4]);

    #pragma unroll
    for (int r = 0; r < 8; r++){
      const float4* qrow = reinterpret_cast<const float4*>(&Qs[(warp*8 + r)*36]);
      float s = 0.f;
      #pragma unroll
      for (int j = 0; j < 8; j++){
        float4 qv = qrow[j];
        s += qv.x*kr[j].x; s += qv.y*kr[j].y;
        s += qv.z*kr[j].z; s += qv.w*kr[j].w;
      }
      float tm = warpMax(s);
      mx[r] = fmaxf(mx[r], tm);
      if (lane == 0) Tmax[(warp*8 + r)*64 + kt] = tm;
    }
  }

  // ---- pass 2: exp + PV on surviving tiles only ----
  float acc[8], l[8];
  #pragma unroll
  for (int r = 0; r < 8; r++){ acc[r] = 0.f; l[r] = 0.f; }

  for (int kt = 0; kt < T_/32; kt++){
    __syncthreads();   // protect Ks/Vs reads of prev iter; also orders Tmax
    unsigned flags = 0;
    #pragma unroll
    for (int r = 0; r < 8; r++)
      if (Tmax[(warp*8 + r)*64 + kt] >= mx[r] - THR_) flags |= 1u << r;

    for (int i = tid; i < 32*32; i += 256){
      int r = i >> 5, m = i & 31;
      Ks[r*36 + m] = Kg[(kt*32 + r)*32 + m];
      Vs[r*36 + m] = Vg[(kt*32 + r)*32 + m];
    }
    __syncthreads();

    if (!flags) continue;   // warp-uniform; both barriers above are unconditional

    float4 kr[8];
    #pragma unroll
    for (int j = 0; j < 8; j++)
      kr[j] = *reinterpret_cast<const float4*>(&Ks[lane*36 + j*4]);

    #pragma unroll
    for (int r = 0; r < 8; r++){
      if (!(flags & (1u << r))) continue;
      const float4* qrow = reinterpret_cast<const float4*>(&Qs[(warp*8 + r)*36]);
      float s = 0.f;
      #pragma unroll
      for (int j = 0; j < 8; j++){
        float4 qv = qrow[j];
        s += qv.x*kr[j].x; s += qv.y*kr[j].y;
        s += qv.z*kr[j].z; s += qv.w*kr[j].w;
      }
      float p = __expf(s - mx[r]);   // exact max: p <= 1, no rescaling
      l[r] += warpSum(p);
      Psh[(warp*8 + r)*32 + lane] = p;
    }
    __syncwarp();

    float vcol[32];
    #pragma unroll
    for (int k = 0; k < 32; k++) vcol[k] = Vs[k*36 + lane];
    #pragma unroll
    for (int r = 0; r < 8; r++){
      if (!(flags & (1u << r))) continue;
      const float4* prow = reinterpret_cast<const float4*>(&Psh[(warp*8 + r)*32]);
      float a = acc[r];
      #pragma unroll
      for (int j = 0; j < 8; j++){
        float4 p4 = prow[j];
        a += p4.x*vcol[j*4+0]; a += p4.y*vcol[j*4+1];
        a += p4.z*vcol[j*4+2]; a += p4.w*vcol[j*4+3];
      }
      acc[r] = a;
    }
  }

  // ---- epilogue: out = acc/l ; cosine vs memories[b,t] ----
  #pragma unroll
  for (int r = 0; r < 8; r++){
    int t = qbase + warp*8 + r;
    float o  = acc[r] / l[r];
    float mv = g_mem[(b*T_ + t)*32 + lane];
    float dot = warpSum(o*mv);
    float no  = warpSum(o*o);
    float nm2 = warpSum(mv*mv);
    if (lane == 0)
      out[(b*T_ + t)*E_ + e] =
          dot / (fmaxf(sqrtf(no), EPS_) * fmaxf(sqrtf(nm2), EPS_));
  }
}

// ---------------------------------------------------------------------------
extern "C" void kernel_launch(void* const* d_in, const int* in_sizes, int n_in,
                              void* d_out, int out_size)
{
  const float* x      = (const float*)d_in[0];
  const float* hidden = (const float*)d_in[1];
  const float* memory = (const float*)d_in[2];
  const float* Wq     = (const float*)d_in[3];
  const float* Wk     = (const float*)d_in[4];
  const float* Wv     = (const float*)d_in[5];
  const float* iq     = (const float*)d_in[6];
  float* out = (float*)d_out;

  mem_kernel<<<B_*T_/4, 128>>>(x, memory, iq);
  qkv_kernel<<<dim3(B_*T_/64, E_), 256>>>(hidden, Wq, Wk, Wv);
  attn_kernel<<<dim3(T_/64, E_*B_), 256>>>(out);
}

// round 8
// speedup vs baseline: 4.1931x; 3.7650x over previous
#include <cuda_runtime.h>
#include <cuda_bf16.h>
#include <math.h>

#define B_ 8
#define T_ 2048
#define H_ 64
#define M_ 32
#define S_ 20
#define E_ 3
#define IN_ 32
#define EPS_ 1e-8f
#define THR_ 30.0f   // bf16 score err ~<2; dropped-tile mass <= 32*e^-26, << 1e-3 tol

// Scratch (allocation-free rule: __device__ globals)
__device__ float g_mem[B_*T_*M_];
__device__ float g_Q[E_*B_*T_*M_];
__device__ float g_K[E_*B_*T_*M_];
__device__ float g_V[E_*B_*T_*M_];
__device__ __nv_bfloat16 g_Qb[E_*B_*T_*M_];
__device__ __nv_bfloat16 g_Kb[E_*B_*T_*M_];

__device__ __forceinline__ float warpSum(float v){
  #pragma unroll
  for (int o=16;o>0;o>>=1) v += __shfl_xor_sync(0xffffffffu, v, o);
  return v;
}

__device__ __forceinline__ void mma16816(float* c, const unsigned* a,
                                         unsigned b0, unsigned b1){
  asm volatile(
    "mma.sync.aligned.m16n8k16.row.col.f32.bf16.bf16.f32 "
    "{%0,%1,%2,%3}, {%4,%5,%6,%7}, {%8,%9}, {%0,%1,%2,%3};\n"
    : "+f"(c[0]), "+f"(c[1]), "+f"(c[2]), "+f"(c[3])
    : "r"(a[0]), "r"(a[1]), "r"(a[2]), "r"(a[3]), "r"(b0), "r"(b1));
}

// ---------------------------------------------------------------------------
// Kernel 1: memories = softmax(x@IQ @ memory^T) @ memory   per (b,t)
// ---------------------------------------------------------------------------
__global__ void mem_kernel(const float* __restrict__ x,
                           const float* __restrict__ memory,
                           const float* __restrict__ iq)
{
  __shared__ float IQs[IN_*M_];
  __shared__ float MEMs[S_*M_];
  int tid = threadIdx.x;
  for (int i = tid; i < IN_*M_; i += 128) IQs[i]  = iq[i];
  for (int i = tid; i < S_*M_;  i += 128) MEMs[i] = memory[i];
  __syncthreads();

  int warp = tid >> 5, lane = tid & 31;
  int bt = blockIdx.x*4 + warp;

  float xv = x[bt*IN_ + lane];
  float q = 0.f;
  #pragma unroll
  for (int i = 0; i < IN_; i++)
    q += __shfl_sync(0xffffffffu, xv, i) * IQs[i*M_ + lane];

  float sc[S_];
  float mx = -INFINITY;
  #pragma unroll
  for (int s = 0; s < S_; s++){
    float v = warpSum(q * MEMs[s*M_ + lane]);
    sc[s] = v; mx = fmaxf(mx, v);
  }
  float sum = 0.f;
  #pragma unroll
  for (int s = 0; s < S_; s++){ sc[s] = __expf(sc[s]-mx); sum += sc[s]; }
  float m = 0.f;
  #pragma unroll
  for (int s = 0; s < S_; s++) m += sc[s]*MEMs[s*M_ + lane];
  g_mem[bt*M_ + lane] = m / sum;
}

// ---------------------------------------------------------------------------
// Kernel 2: Q/K/V projections; also emit bf16 copies of Q,K for pass-1 MMA.
// ---------------------------------------------------------------------------
__global__ __launch_bounds__(256) void qkv_kernel(const float* __restrict__ hidden,
                           const float* __restrict__ Wq,
                           const float* __restrict__ Wk,
                           const float* __restrict__ Wv)
{
  __shared__ float Wqs[H_*M_], Wks[H_*M_], Wvs[H_*M_];
  int e = blockIdx.y;
  int tid = threadIdx.x;
  for (int i = tid; i < H_*M_; i += 256){
    Wqs[i] = Wq[e*H_*M_ + i];
    Wks[i] = Wk[e*H_*M_ + i];
    Wvs[i] = Wv[e*H_*M_ + i];
  }
  __syncthreads();

  int warp = tid >> 5, lane = tid & 31;
  int rowBase = blockIdx.x*64 + warp*8;
  #pragma unroll
  for (int rr = 0; rr < 8; rr++){
    int row = rowBase + rr;
    long gr = (long)e*B_*T_ + row;
    float h0 = hidden[gr*H_ + lane];
    float h1 = hidden[gr*H_ + 32 + lane];
    float q = 0.f, k = 0.f, v = 0.f;
    #pragma unroll
    for (int h = 0; h < 32; h++){
      float hv = __shfl_sync(0xffffffffu, h0, h);
      q += hv*Wqs[h*M_+lane]; k += hv*Wks[h*M_+lane]; v += hv*Wvs[h*M_+lane];
    }
    #pragma unroll
    for (int h = 0; h < 32; h++){
      float hv = __shfl_sync(0xffffffffu, h1, h);
      q += hv*Wqs[(h+32)*M_+lane]; k += hv*Wks[(h+32)*M_+lane]; v += hv*Wvs[(h+32)*M_+lane];
    }
    g_Q[gr*M_+lane] = q; g_K[gr*M_+lane] = k; g_V[gr*M_+lane] = v;
    g_Qb[gr*M_+lane] = __float2bfloat16(q);
    g_Kb[gr*M_+lane] = __float2bfloat16(k);
  }
}

// ---------------------------------------------------------------------------
// Kernel 3: attention.
//  Pass 1 (bf16 HMMA): per-(row, 32-key-tile) max + per-row max. Block = 128
//  query rows of one (e,b); 8 warps x 16 rows; all warps sweep all 2048 keys
//  from a shared staged K tile (128 keys, 80B padded rows, conflict-free).
//  Pass 2 (fp32, per-warp, no block syncs): for surviving tiles only,
//  exact scores via coalesced K/V column loads + warp reductions; exp uses
//  the approximate row max (softmax shift-invariance => exact after acc/l).
//  Epilogue: cosine vs memories.
// ---------------------------------------------------------------------------
// dynamic smem layout (bytes):
//  [0, 10240)            Kst: 128 keys x 40 bf16 (80B padded rows)
//  [10240, 43520)        Tmax: 128 rows x 65 f32
//  [43520, 59904)        accS: 128 rows x 32 f32
//  [59904, 60416)        lS:   128 f32
//  [60416, 60928)        Rmax: 128 f32
#define ATTN_SMEM_ 60928

__global__ __launch_bounds__(256) void attn_kernel(float* __restrict__ out)
{
  extern __shared__ char smem[];
  __nv_bfloat16* Kst = (__nv_bfloat16*)smem;
  float* Tmax  = (float*)(smem + 10240);
  float* accS  = (float*)(smem + 43520);
  float* lS    = (float*)(smem + 59904);
  float* RmaxS = (float*)(smem + 60416);

  int tid = threadIdx.x, w = tid >> 5, lane = tid & 31;
  int gid = lane >> 2, tig = lane & 3;
  int eb = blockIdx.y, e = eb / B_, b = eb % B_;
  size_t ebT = (size_t)eb * T_;
  int qbase = blockIdx.x * 128;
  int row_lo = qbase + w*16 + gid, row_hi = row_lo + 8;

  // persistent A fragments (Q bf16, both k-chunks), direct from global
  unsigned a[8];
  {
    const __nv_bfloat16* q0 = g_Qb + (ebT + row_lo)*M_;
    const __nv_bfloat16* q1 = g_Qb + (ebT + row_hi)*M_;
    a[0]=*(const unsigned*)(q0+2*tig);    a[1]=*(const unsigned*)(q1+2*tig);
    a[2]=*(const unsigned*)(q0+2*tig+8);  a[3]=*(const unsigned*)(q1+2*tig+8);
    a[4]=*(const unsigned*)(q0+2*tig+16); a[5]=*(const unsigned*)(q1+2*tig+16);
    a[6]=*(const unsigned*)(q0+2*tig+24); a[7]=*(const unsigned*)(q1+2*tig+24);
  }

  for (int i = tid; i < 128*32; i += 256) accS[i] = 0.f;
  for (int i = tid; i < 128;    i += 256) lS[i]   = 0.f;

  float mlo = -INFINITY, mhi = -INFINITY;

  const unsigned* Kbg = (const unsigned*)(g_Kb + ebT*M_);  // [key][16 uints]
  unsigned pf[8];
  #pragma unroll
  for (int i = 0; i < 8; i++) pf[i] = Kbg[tid + i*256];    // chunk 0

  for (int c = 0; c < 16; c++){
    __syncthreads();                         // buffer free (also covers accS init)
    #pragma unroll
    for (int i = 0; i < 8; i++){
      int lidx = tid + i*256;                // key_local = lidx/16, j = lidx%16
      *(unsigned*)((char*)Kst + (lidx >> 4)*80 + (lidx & 15)*4) = pf[i];
    }
    __syncthreads();                         // buffer ready
    if (c < 15){
      #pragma unroll
      for (int i = 0; i < 8; i++) pf[i] = Kbg[(c+1)*2048 + tid + i*256];
    }

    #pragma unroll
    for (int t = 0; t < 4; t++){
      int kt = c*4 + t;
      float tlo = -INFINITY, thi = -INFINITY;
      #pragma unroll
      for (int nb = 0; nb < 4; nb++){
        const char* bp = (const char*)Kst + (t*32 + nb*8 + gid)*80 + tig*4;
        unsigned b0 = *(const unsigned*)(bp);
        unsigned b1 = *(const unsigned*)(bp + 16);
        unsigned b2 = *(const unsigned*)(bp + 32);
        unsigned b3 = *(const unsigned*)(bp + 48);
        float cc[4] = {0.f, 0.f, 0.f, 0.f};
        mma16816(cc, a,   b0, b1);           // k-chunk 0 (m 0..15)
        mma16816(cc, a+4, b2, b3);           // k-chunk 1 (m 16..31)
        tlo = fmaxf(tlo, fmaxf(cc[0], cc[1]));
        thi = fmaxf(thi, fmaxf(cc[2], cc[3]));
      }
      tlo = fmaxf(tlo, __shfl_xor_sync(0xffffffffu, tlo, 1));
      tlo = fmaxf(tlo, __shfl_xor_sync(0xffffffffu, tlo, 2));
      thi = fmaxf(thi, __shfl_xor_sync(0xffffffffu, thi, 1));
      thi = fmaxf(thi, __shfl_xor_sync(0xffffffffu, thi, 2));
      if (tig == 0){
        Tmax[(w*16 + gid)*65 + kt]     = tlo;
        Tmax[(w*16 + gid + 8)*65 + kt] = thi;
      }
      mlo = fmaxf(mlo, tlo); mhi = fmaxf(mhi, thi);
    }
  }
  if (tig == 0){ RmaxS[w*16 + gid] = mlo; RmaxS[w*16 + gid + 8] = mhi; }
  __syncwarp();

  // ---- pass 2: per-warp, exact fp32, surviving tiles only ----
  const float* Kg = g_K + ebT*M_;
  const float* Vg = g_V + ebT*M_;
  for (int kt = 0; kt < 64; kt++){
    bool pr = false;
    if (lane < 16)
      pr = Tmax[(w*16 + lane)*65 + kt] >= RmaxS[w*16 + lane] - THR_;
    unsigned rmask = __ballot_sync(0xffffffffu, pr) & 0xFFFFu;
    if (!rmask) continue;

    float kreg[32], vreg[32];
    #pragma unroll
    for (int k = 0; k < 32; k++){
      size_t off = (size_t)(kt*32 + k)*32 + lane;   // coalesced per k
      kreg[k] = __ldg(&Kg[off]);
      vreg[k] = __ldg(&Vg[off]);
    }

    while (rmask){
      int r = __ffs(rmask) - 1; rmask &= rmask - 1;   // warp-uniform
      int row = w*16 + r;
      float q   = __ldg(&g_Q[(ebT + qbase + row)*M_ + lane]);
      float rmx = RmaxS[row];
      float acc = accS[row*32 + lane];
      float lv  = lS[row];
      #pragma unroll
      for (int k = 0; k < 32; k++){
        float sp = q * kreg[k];
        sp += __shfl_xor_sync(0xffffffffu, sp, 16);
        sp += __shfl_xor_sync(0xffffffffu, sp, 8);
        sp += __shfl_xor_sync(0xffffffffu, sp, 4);
        sp += __shfl_xor_sync(0xffffffffu, sp, 2);
        sp += __shfl_xor_sync(0xffffffffu, sp, 1);
        float p = __expf(sp - rmx);    // shift cancels in acc/l exactly
        acc += p * vreg[k];
        lv  += p;
      }
      accS[row*32 + lane] = acc;
      lS[row] = lv;                    // all lanes write same value
    }
  }
  __syncwarp();

  // ---- epilogue: cosine(out_row, memories[b,t]) ----
  for (int r = 0; r < 16; r++){
    int row = w*16 + r, t = qbase + row;
    float o  = accS[row*32 + lane] / lS[row];
    float mv = g_mem[((size_t)b*T_ + t)*M_ + lane];
    float d  = warpSum(o*mv);
    float n1 = warpSum(o*o);
    float n2 = warpSum(mv*mv);
    if (lane == 0)
      out[((size_t)b*T_ + t)*E_ + e] =
          d / (fmaxf(sqrtf(n1), EPS_) * fmaxf(sqrtf(n2), EPS_));
  }
}

// ---------------------------------------------------------------------------
extern "C" void kernel_launch(void* const* d_in, const int* in_sizes, int n_in,
                              void* d_out, int out_size)
{
  const float* x      = (const float*)d_in[0];
  const float* hidden = (const float*)d_in[1];
  const float* memory = (const float*)d_in[2];
  const float* Wq     = (const float*)d_in[3];
  const float* Wk     = (const float*)d_in[4];
  const float* Wv     = (const float*)d_in[5];
  const float* iq     = (const float*)d_in[6];
  float* out = (float*)d_out;

  cudaFuncSetAttribute(attn_kernel, cudaFuncAttributeMaxDynamicSharedMemorySize,
                       ATTN_SMEM_);

  mem_kernel<<<B_*T_/4, 128>>>(x, memory, iq);
  qkv_kernel<<<dim3(B_*T_/64, E_), 256>>>(hidden, Wq, Wk, Wv);
  attn_kernel<<<dim3(T_/128, E_*B_), 256, ATTN_SMEM_>>>(out);
}

// round 10
// speedup vs baseline: 4.9476x; 1.1799x over previous
#include <cuda_runtime.h>
#include <cuda_bf16.h>
#include <cuda_fp16.h>
#include <math.h>

#define B_ 8
#define T_ 2048
#define H_ 64
#define M_ 32
#define S_ 20
#define E_ 3
#define IN_ 32
#define EPS_ 1e-8f
#define THR_ 30.0f  // bf16 MMA err ~<3 + half Tmax err ~<1 << 30; dropped mass ~e^-26

// Scratch (allocation-free rule: __device__ globals)
__device__ float g_mem[B_*T_*M_];
__device__ float g_Q[E_*B_*T_*M_];
__device__ float g_K[E_*B_*T_*M_];
__device__ float g_V[E_*B_*T_*M_];
__device__ __nv_bfloat16 g_Qb[E_*B_*T_*M_];
__device__ __nv_bfloat16 g_Kb[E_*B_*T_*M_];
__device__ __half g_Tmaxh[E_*B_*T_*64];   // per-(row, key-tile) approx max
__device__ float g_Rmax[E_*B_*T_];        // per-row approx max

__device__ __forceinline__ float warpSum(float v){
  #pragma unroll
  for (int o=16;o>0;o>>=1) v += __shfl_xor_sync(0xffffffffu, v, o);
  return v;
}

__device__ __forceinline__ void mma16816(float* c, const unsigned* a,
                                         unsigned b0, unsigned b1){
  asm volatile(
    "mma.sync.aligned.m16n8k16.row.col.f32.bf16.bf16.f32 "
    "{%0,%1,%2,%3}, {%4,%5,%6,%7}, {%8,%9}, {%0,%1,%2,%3};\n"
    : "+f"(c[0]), "+f"(c[1]), "+f"(c[2]), "+f"(c[3])
    : "r"(a[0]), "r"(a[1]), "r"(a[2]), "r"(a[3]), "r"(b0), "r"(b1));
}

// ---------------------------------------------------------------------------
// Kernel 1: memories = softmax(x@IQ @ memory^T) @ memory   per (b,t)
// ---------------------------------------------------------------------------
__global__ void mem_kernel(const float* __restrict__ x,
                           const float* __restrict__ memory,
                           const float* __restrict__ iq)
{
  __shared__ float IQs[IN_*M_];
  __shared__ float MEMs[S_*M_];
  int tid = threadIdx.x;
  for (int i = tid; i < IN_*M_; i += 128) IQs[i]  = iq[i];
  for (int i = tid; i < S_*M_;  i += 128) MEMs[i] = memory[i];
  __syncthreads();

  int warp = tid >> 5, lane = tid & 31;
  int bt = blockIdx.x*4 + warp;

  float xv = x[bt*IN_ + lane];
  float q = 0.f;
  #pragma unroll
  for (int i = 0; i < IN_; i++)
    q += __shfl_sync(0xffffffffu, xv, i) * IQs[i*M_ + lane];

  float sc[S_];
  float mx = -INFINITY;
  #pragma unroll
  for (int s = 0; s < S_; s++){
    float v = warpSum(q * MEMs[s*M_ + lane]);
    sc[s] = v; mx = fmaxf(mx, v);
  }
  float sum = 0.f;
  #pragma unroll
  for (int s = 0; s < S_; s++){ sc[s] = __expf(sc[s]-mx); sum += sc[s]; }
  float m = 0.f;
  #pragma unroll
  for (int s = 0; s < S_; s++) m += sc[s]*MEMs[s*M_ + lane];
  g_mem[bt*M_ + lane] = m / sum;
}

// ---------------------------------------------------------------------------
// Kernel 2: Q/K/V projections; also emit bf16 copies of Q,K for pass-1 MMA.
// ---------------------------------------------------------------------------
__global__ __launch_bounds__(256) void qkv_kernel(const float* __restrict__ hidden,
                           const float* __restrict__ Wq,
                           const float* __restrict__ Wk,
                           const float* __restrict__ Wv)
{
  __shared__ float Wqs[H_*M_], Wks[H_*M_], Wvs[H_*M_];
  int e = blockIdx.y;
  int tid = threadIdx.x;
  for (int i = tid; i < H_*M_; i += 256){
    Wqs[i] = Wq[e*H_*M_ + i];
    Wks[i] = Wk[e*H_*M_ + i];
    Wvs[i] = Wv[e*H_*M_ + i];
  }
  __syncthreads();

  int warp = tid >> 5, lane = tid & 31;
  int rowBase = blockIdx.x*64 + warp*8;
  #pragma unroll
  for (int rr = 0; rr < 8; rr++){
    int row = rowBase + rr;
    long gr = (long)e*B_*T_ + row;
    float h0 = hidden[gr*H_ + lane];
    float h1 = hidden[gr*H_ + 32 + lane];
    float q = 0.f, k = 0.f, v = 0.f;
    #pragma unroll
    for (int h = 0; h < 32; h++){
      float hv = __shfl_sync(0xffffffffu, h0, h);
      q += hv*Wqs[h*M_+lane]; k += hv*Wks[h*M_+lane]; v += hv*Wvs[h*M_+lane];
    }
    #pragma unroll
    for (int h = 0; h < 32; h++){
      float hv = __shfl_sync(0xffffffffu, h1, h);
      q += hv*Wqs[(h+32)*M_+lane]; k += hv*Wks[(h+32)*M_+lane]; v += hv*Wvs[(h+32)*M_+lane];
    }
    g_Q[gr*M_+lane] = q; g_K[gr*M_+lane] = k; g_V[gr*M_+lane] = v;
    g_Qb[gr*M_+lane] = __float2bfloat16(q);
    g_Kb[gr*M_+lane] = __float2bfloat16(k);
  }
}

// ---------------------------------------------------------------------------
// Kernel 3a: pass 1 (bf16 HMMA) — per-(row, 32-key-tile) max + per-row max.
// Block = 128 query rows of one (e,b); 8 warps x 16 rows; staged 128-key
// bf16 tiles (80B padded rows). Lean smem/regs => 4-5 blocks/SM.
// ---------------------------------------------------------------------------
__global__ __launch_bounds__(256) void attn_pass1()
{
  __shared__ char KstRaw[10240];          // 128 keys x 40 bf16 (80B rows)
  __shared__ __half Tmx[128*64];          // [row][tile] 16KB

  int tid = threadIdx.x, w = tid >> 5, lane = tid & 31;
  int gid = lane >> 2, tig = lane & 3;
  int eb = blockIdx.y;
  size_t ebT = (size_t)eb * T_;
  int qbase = blockIdx.x * 128;
  int row_lo = qbase + w*16 + gid, row_hi = row_lo + 8;

  unsigned a[8];
  {
    const __nv_bfloat16* q0 = g_Qb + (ebT + row_lo)*M_;
    const __nv_bfloat16* q1 = g_Qb + (ebT + row_hi)*M_;
    a[0]=*(const unsigned*)(q0+2*tig);    a[1]=*(const unsigned*)(q1+2*tig);
    a[2]=*(const unsigned*)(q0+2*tig+8);  a[3]=*(const unsigned*)(q1+2*tig+8);
    a[4]=*(const unsigned*)(q0+2*tig+16); a[5]=*(const unsigned*)(q1+2*tig+16);
    a[6]=*(const unsigned*)(q0+2*tig+24); a[7]=*(const unsigned*)(q1+2*tig+24);
  }

  float mlo = -INFINITY, mhi = -INFINITY;

  const unsigned* Kbg = (const unsigned*)(g_Kb + ebT*M_);
  unsigned pf[8];
  #pragma unroll
  for (int i = 0; i < 8; i++) pf[i] = Kbg[tid + i*256];

  for (int c = 0; c < 16; c++){
    __syncthreads();
    #pragma unroll
    for (int i = 0; i < 8; i++){
      int lidx = tid + i*256;
      *(unsigned*)(KstRaw + (lidx >> 4)*80 + (lidx & 15)*4) = pf[i];
    }
    __syncthreads();
    if (c < 15){
      #pragma unroll
      for (int i = 0; i < 8; i++) pf[i] = Kbg[(c+1)*2048 + tid + i*256];
    }

    #pragma unroll
    for (int t = 0; t < 4; t++){
      int kt = c*4 + t;
      float tlo = -INFINITY, thi = -INFINITY;
      #pragma unroll
      for (int nb = 0; nb < 4; nb++){
        const char* bp = KstRaw + (t*32 + nb*8 + gid)*80 + tig*4;
        unsigned b0 = *(const unsigned*)(bp);
        unsigned b1 = *(const unsigned*)(bp + 16);
        unsigned b2 = *(const unsigned*)(bp + 32);
        unsigned b3 = *(const unsigned*)(bp + 48);
        float cc[4] = {0.f, 0.f, 0.f, 0.f};
        mma16816(cc, a,   b0, b1);
        mma16816(cc, a+4, b2, b3);
        tlo = fmaxf(tlo, fmaxf(cc[0], cc[1]));
        thi = fmaxf(thi, fmaxf(cc[2], cc[3]));
      }
      tlo = fmaxf(tlo, __shfl_xor_sync(0xffffffffu, tlo, 1));
      tlo = fmaxf(tlo, __shfl_xor_sync(0xffffffffu, tlo, 2));
      thi = fmaxf(thi, __shfl_xor_sync(0xffffffffu, thi, 1));
      thi = fmaxf(thi, __shfl_xor_sync(0xffffffffu, thi, 2));
      if (tig == 0){
        Tmx[(w*16 + gid)*64 + kt]     = __float2half_rn(tlo);
        Tmx[(w*16 + gid + 8)*64 + kt] = __float2half_rn(thi);
      }
      mlo = fmaxf(mlo, tlo); mhi = fmaxf(mhi, thi);
    }
  }
  if (tig == 0){
    g_Rmax[ebT + qbase + w*16 + gid]     = mlo;
    g_Rmax[ebT + qbase + w*16 + gid + 8] = mhi;
  }
  __syncthreads();
  // coalesced copy Tmx -> global (128 rows * 64 tiles of half = 4096 u32)
  unsigned* dst = (unsigned*)(g_Tmaxh + (ebT + qbase)*64);
  const unsigned* src = (const unsigned*)Tmx;
  for (int i = tid; i < 4096; i += 256) dst[i] = src[i];
}

// ---------------------------------------------------------------------------
// Kernel 3b: pass 2 — survivors only, exact fp32, per-warp (no block syncs
// in the loop). lane = key for scoring: K tile staged per-warp in smem
// (32x33 f32, conflict-free), 4 independent FMA chains fed by shfl(q,m),
// ONE exp per 32 keys, PV via shfl(p,k) broadcasts into 2 FMA chains.
// Epilogue: cosine vs memories.
// dynamic smem layout (bytes):
//  [0, 33792)       Kf: 8 warps x (32x33) f32
//  [33792, 50176)   accS: 128 rows x 32 f32
//  [50176, 66560)   Tmx: 128 x 64 half
//  [66560, 67072)   lS: 128 f32
//  [67072, 67584)   Rm: 128 f32
// ---------------------------------------------------------------------------
#define P2_SMEM_ 67584

__global__ __launch_bounds__(256, 2) void attn_pass2(float* __restrict__ out)
{
  extern __shared__ char sm2[];
  float*  Kf   = (float*)sm2;
  float*  accS = (float*)(sm2 + 33792);
  __half* Tmx  = (__half*)(sm2 + 50176);
  float*  lS   = (float*)(sm2 + 66560);
  float*  Rm   = (float*)(sm2 + 67072);

  int tid = threadIdx.x, w = tid >> 5, lane = tid & 31;
  int eb = blockIdx.y, e = eb / B_, b = eb % B_;
  size_t ebT = (size_t)eb * T_;
  int qbase = blockIdx.x * 128;

  {
    const unsigned* src = (const unsigned*)(g_Tmaxh + (ebT + qbase)*64);
    unsigned* dstT = (unsigned*)Tmx;
    for (int i = tid; i < 4096; i += 256){ dstT[i] = src[i]; accS[i] = 0.f; }
    for (int i = tid; i < 128;  i += 256){ Rm[i] = g_Rmax[ebT + qbase + i]; lS[i] = 0.f; }
  }
  __syncthreads();

  const float* Kg = g_K + ebT*M_;
  const float* Vg = g_V + ebT*M_;
  const float* Qg = g_Q + (ebT + qbase)*M_;
  float* Kw = Kf + w*1056;
  int rowb = w*16;

  for (int kt = 0; kt < 64; kt++){
    bool pr = false;
    if (lane < 16)
      pr = __half2float(Tmx[(rowb + lane)*64 + kt]) >= Rm[rowb + lane] - THR_;
    unsigned rmask = __ballot_sync(0xffffffffu, pr) & 0xFFFFu;
    if (!rmask) continue;

    const float* Kt = Kg + (size_t)kt*1024;
    const float* Vt = Vg + (size_t)kt*1024;
    float vreg[32];
    #pragma unroll
    for (int k = 0; k < 32; k++){
      Kw[k*33 + lane] = __ldg(&Kt[k*32 + lane]);   // coalesced, conflict-free STS
      vreg[k]         = __ldg(&Vt[k*32 + lane]);
    }
    __syncwarp();

    while (rmask){
      int r = __ffs(rmask) - 1; rmask &= rmask - 1;   // warp-uniform
      int row = rowb + r;
      float q = __ldg(&Qg[(size_t)row*32 + lane]);    // lane = m
      // scores: lane = key; 4 independent chains, shfl-broadcast q
      float s0 = 0.f, s1 = 0.f, s2 = 0.f, s3 = 0.f;
      #pragma unroll
      for (int m = 0; m < 8; m++){
        s0 = fmaf(__shfl_sync(0xffffffffu, q, m),      Kw[lane*33 + m],      s0);
        s1 = fmaf(__shfl_sync(0xffffffffu, q, m + 8),  Kw[lane*33 + m + 8],  s1);
        s2 = fmaf(__shfl_sync(0xffffffffu, q, m + 16), Kw[lane*33 + m + 16], s2);
        s3 = fmaf(__shfl_sync(0xffffffffu, q, m + 24), Kw[lane*33 + m + 24], s3);
      }
      float s = (s0 + s1) + (s2 + s3);
      float p = __expf(s - Rm[row]);     // ONE exp covers 32 keys
      float lv = warpSum(p);
      if (lane == 0) lS[row] += lv;
      // PV: lane = m; broadcast p from key lanes, 2 independent chains
      float a0 = accS[row*32 + lane], a1 = 0.f;
      #pragma unroll
      for (int k = 0; k < 16; k++){
        a0 = fmaf(__shfl_sync(0xffffffffu, p, k),      vreg[k],      a0);
        a1 = fmaf(__shfl_sync(0xffffffffu, p, k + 16), vreg[k + 16], a1);
      }
      accS[row*32 + lane] = a0 + a1;
    }
    __syncwarp();
  }
  __syncwarp();

  // epilogue: cosine(out_row, memories[b,t])
  for (int r = 0; r < 16; r++){
    int row = rowb + r, t = qbase + row;
    float o  = accS[row*32 + lane] / lS[row];
    float mv = g_mem[((size_t)b*T_ + t)*M_ + lane];
    float d  = warpSum(o*mv);
    float n1 = warpSum(o*o);
    float n2 = warpSum(mv*mv);
    if (lane == 0)
      out[((size_t)b*T_ + t)*E_ + e] =
          d / (fmaxf(sqrtf(n1), EPS_) * fmaxf(sqrtf(n2), EPS_));
  }
}

// ---------------------------------------------------------------------------
extern "C" void kernel_launch(void* const* d_in, const int* in_sizes, int n_in,
                              void* d_out, int out_size)
{
  const float* x      = (const float*)d_in[0];
  const float* hidden = (const float*)d_in[1];
  const float* memory = (const float*)d_in[2];
  const float* Wq     = (const float*)d_in[3];
  const float* Wk     = (const float*)d_in[4];
  const float* Wv     = (const float*)d_in[5];
  const float* iq     = (const float*)d_in[6];
  float* out = (float*)d_out;

  cudaFuncSetAttribute(attn_pass2, cudaFuncAttributeMaxDynamicSharedMemorySize,
                       P2_SMEM_);

  mem_kernel<<<B_*T_/4, 128>>>(x, memory, iq);
  qkv_kernel<<<dim3(B_*T_/64, E_), 256>>>(hidden, Wq, Wk, Wv);
  attn_pass1<<<dim3(T_/128, E_*B_), 256>>>();
  attn_pass2<<<dim3(T_/128, E_*B_), 256, P2_SMEM_>>>(out);
}

// round 12
// speedup vs baseline: 5.1071x; 1.0322x over previous
#include <cuda_runtime.h>
#include <cuda_bf16.h>
#include <cuda_fp16.h>
#include <math.h>

#define B_ 8
#define T_ 2048
#define H_ 64
#define M_ 32
#define S_ 20
#define E_ 3
#define IN_ 32
#define EPS_ 1e-8f
#define THR_ 30.0f  // bf16 MMA err ~<3 + half Tmax err ~<1 << 30; dropped mass ~e^-26

// Scratch (allocation-free rule: __device__ globals)
__device__ float g_mem[B_*T_*M_];
__device__ float g_Q[E_*B_*T_*M_];
__device__ float g_K[E_*B_*T_*M_];
__device__ float g_V[E_*B_*T_*M_];
__device__ __nv_bfloat16 g_Qb[E_*B_*T_*M_];
__device__ __nv_bfloat16 g_Kb[E_*B_*T_*M_];
__device__ __half g_Tmaxh[E_*B_*T_*64];   // per-(row, key-tile) approx max
__device__ float g_Rmax[E_*B_*T_];        // per-row approx max

__device__ __forceinline__ float warpSum(float v){
  #pragma unroll
  for (int o=16;o>0;o>>=1) v += __shfl_xor_sync(0xffffffffu, v, o);
  return v;
}
__device__ __forceinline__ float warpMax(float v){
  #pragma unroll
  for (int o=16;o>0;o>>=1) v = fmaxf(v, __shfl_xor_sync(0xffffffffu, v, o));
  return v;
}

__device__ __forceinline__ void mma16816(float* c, const unsigned* a,
                                         unsigned b0, unsigned b1){
  asm volatile(
    "mma.sync.aligned.m16n8k16.row.col.f32.bf16.bf16.f32 "
    "{%0,%1,%2,%3}, {%4,%5,%6,%7}, {%8,%9}, {%0,%1,%2,%3};\n"
    : "+f"(c[0]), "+f"(c[1]), "+f"(c[2]), "+f"(c[3])
    : "r"(a[0]), "r"(a[1]), "r"(a[2]), "r"(a[3]), "r"(b0), "r"(b1));
}

// ---------------------------------------------------------------------------
// Kernel 1: memories = softmax(x@IQ @ memory^T) @ memory   per (b,t)
// lane=m for q/memories phases, lane=s for the scoring phase:
// 32 q-broadcast shfls serve all 20 slots at once; ONE exp per lane.
// MEMT padded to 33-stride: conflict-free both row-wise and column-wise.
// ---------------------------------------------------------------------------
__global__ void mem_kernel(const float* __restrict__ x,
                           const float* __restrict__ memory,
                           const float* __restrict__ iq)
{
  __shared__ float IQs[IN_*M_];
  __shared__ float MEMT[33*33];
  int tid = threadIdx.x;
  for (int i = tid; i < IN_*M_; i += 128) IQs[i] = iq[i];
  for (int i = tid; i < 33*33;  i += 128){
    int s = i / 33, m = i % 33;
    MEMT[i] = (s < S_ && m < M_) ? memory[s*M_ + m] : 0.f;
  }
  __syncthreads();

  int warp = tid >> 5, lane = tid & 31;
  int bt = blockIdx.x*4 + warp;

  // q[m], lane = m
  float xv = x[bt*IN_ + lane];
  float q = 0.f;
  #pragma unroll
  for (int i = 0; i < IN_; i++)
    q += __shfl_sync(0xffffffffu, xv, i) * IQs[i*M_ + lane];

  // scores, lane = s (lanes >= 20 masked out; padded MEMT rows are zero)
  float sc = 0.f;
  #pragma unroll
  for (int m = 0; m < M_; m++)
    sc = fmaf(__shfl_sync(0xffffffffu, q, m), MEMT[lane*33 + m], sc);
  float mx = warpMax(lane < S_ ? sc : -INFINITY);
  float p  = (lane < S_) ? __expf(sc - mx) : 0.f;
  float sum = warpSum(p);

  // memories[m], lane = m
  float mval = 0.f;
  #pragma unroll
  for (int s = 0; s < S_; s++)
    mval = fmaf(__shfl_sync(0xffffffffu, p, s), MEMT[s*33 + lane], mval);
  g_mem[bt*M_ + lane] = mval / sum;
}

// ---------------------------------------------------------------------------
// Kernel 2: Q/K/V projections; also emit bf16 copies of Q,K for pass-1 MMA.
// ---------------------------------------------------------------------------
__global__ __launch_bounds__(256) void qkv_kernel(const float* __restrict__ hidden,
                           const float* __restrict__ Wq,
                           const float* __restrict__ Wk,
                           const float* __restrict__ Wv)
{
  __shared__ float Wqs[H_*M_], Wks[H_*M_], Wvs[H_*M_];
  int e = blockIdx.y;
  int tid = threadIdx.x;
  for (int i = tid; i < H_*M_; i += 256){
    Wqs[i] = Wq[e*H_*M_ + i];
    Wks[i] = Wk[e*H_*M_ + i];
    Wvs[i] = Wv[e*H_*M_ + i];
  }
  __syncthreads();

  int warp = tid >> 5, lane = tid & 31;
  int rowBase = blockIdx.x*64 + warp*8;
  #pragma unroll
  for (int rr = 0; rr < 8; rr++){
    int row = rowBase + rr;
    long gr = (long)e*B_*T_ + row;
    float h0 = hidden[gr*H_ + lane];
    float h1 = hidden[gr*H_ + 32 + lane];
    float q = 0.f, k = 0.f, v = 0.f;
    #pragma unroll
    for (int h = 0; h < 32; h++){
      float hv = __shfl_sync(0xffffffffu, h0, h);
      q += hv*Wqs[h*M_+lane]; k += hv*Wks[h*M_+lane]; v += hv*Wvs[h*M_+lane];
    }
    #pragma unroll
    for (int h = 0; h < 32; h++){
      float hv = __shfl_sync(0xffffffffu, h1, h);
      q += hv*Wqs[(h+32)*M_+lane]; k += hv*Wks[(h+32)*M_+lane]; v += hv*Wvs[(h+32)*M_+lane];
    }
    g_Q[gr*M_+lane] = q; g_K[gr*M_+lane] = k; g_V[gr*M_+lane] = v;
    g_Qb[gr*M_+lane] = __float2bfloat16(q);
    g_Kb[gr*M_+lane] = __float2bfloat16(k);
  }
}

// ---------------------------------------------------------------------------
// Kernel 3a: pass 1 (bf16 HMMA) — per-(row, 32-key-tile) max + per-row max.
// ---------------------------------------------------------------------------
__global__ __launch_bounds__(256) void attn_pass1()
{
  __shared__ char KstRaw[10240];          // 128 keys x 40 bf16 (80B rows)
  __shared__ __half Tmx[128*64];          // [row][tile] 16KB

  int tid = threadIdx.x, w = tid >> 5, lane = tid & 31;
  int gid = lane >> 2, tig = lane & 3;
  int eb = blockIdx.y;
  size_t ebT = (size_t)eb * T_;
  int qbase = blockIdx.x * 128;
  int row_lo = qbase + w*16 + gid, row_hi = row_lo + 8;

  unsigned a[8];
  {
    const __nv_bfloat16* q0 = g_Qb + (ebT + row_lo)*M_;
    const __nv_bfloat16* q1 = g_Qb + (ebT + row_hi)*M_;
    a[0]=*(const unsigned*)(q0+2*tig);    a[1]=*(const unsigned*)(q1+2*tig);
    a[2]=*(const unsigned*)(q0+2*tig+8);  a[3]=*(const unsigned*)(q1+2*tig+8);
    a[4]=*(const unsigned*)(q0+2*tig+16); a[5]=*(const unsigned*)(q1+2*tig+16);
    a[6]=*(const unsigned*)(q0+2*tig+24); a[7]=*(const unsigned*)(q1+2*tig+24);
  }

  float mlo = -INFINITY, mhi = -INFINITY;

  const unsigned* Kbg = (const unsigned*)(g_Kb + ebT*M_);
  unsigned pf[8];
  #pragma unroll
  for (int i = 0; i < 8; i++) pf[i] = Kbg[tid + i*256];

  for (int c = 0; c < 16; c++){
    __syncthreads();
    #pragma unroll
    for (int i = 0; i < 8; i++){
      int lidx = tid + i*256;
      *(unsigned*)(KstRaw + (lidx >> 4)*80 + (lidx & 15)*4) = pf[i];
    }
    __syncthreads();
    if (c < 15){
      #pragma unroll
      for (int i = 0; i < 8; i++) pf[i] = Kbg[(c+1)*2048 + tid + i*256];
    }

    #pragma unroll
    for (int t = 0; t < 4; t++){
      int kt = c*4 + t;
      float tlo = -INFINITY, thi = -INFINITY;
      #pragma unroll
      for (int nb = 0; nb < 4; nb++){
        const char* bp = KstRaw + (t*32 + nb*8 + gid)*80 + tig*4;
        unsigned b0 = *(const unsigned*)(bp);
        unsigned b1 = *(const unsigned*)(bp + 16);
        unsigned b2 = *(const unsigned*)(bp + 32);
        unsigned b3 = *(const unsigned*)(bp + 48);
        float cc[4] = {0.f, 0.f, 0.f, 0.f};
        mma16816(cc, a,   b0, b1);
        mma16816(cc, a+4, b2, b3);
        tlo = fmaxf(tlo, fmaxf(cc[0], cc[1]));
        thi = fmaxf(thi, fmaxf(cc[2], cc[3]));
      }
      tlo = fmaxf(tlo, __shfl_xor_sync(0xffffffffu, tlo, 1));
      tlo = fmaxf(tlo, __shfl_xor_sync(0xffffffffu, tlo, 2));
      thi = fmaxf(thi, __shfl_xor_sync(0xffffffffu, thi, 1));
      thi = fmaxf(thi, __shfl_xor_sync(0xffffffffu, thi, 2));
      if (tig == 0){
        Tmx[(w*16 + gid)*64 + kt]     = __float2half_rn(tlo);
        Tmx[(w*16 + gid + 8)*64 + kt] = __float2half_rn(thi);
      }
      mlo = fmaxf(mlo, tlo); mhi = fmaxf(mhi, thi);
    }
  }
  if (tig == 0){
    g_Rmax[ebT + qbase + w*16 + gid]     = mlo;
    g_Rmax[ebT + qbase + w*16 + gid + 8] = mhi;
  }
  __syncthreads();
  unsigned* dst = (unsigned*)(g_Tmaxh + (ebT + qbase)*64);
  const unsigned* src = (const unsigned*)Tmx;
  for (int i = tid; i < 4096; i += 256) dst[i] = src[i];
}

// ---------------------------------------------------------------------------
// Kernel 3b: pass 2, block-cooperative.
//  Phase A: build per-tile survivor row lists (smem atomics on counters).
//  Main loop: stage EACH K/V tile ONCE per block (all 256 threads; a tile is
//  32 keys x 32 floats = 1024 elems => 4 x 256, reg-prefetch double buffer),
//  then all 8 warps process that tile's surviving rows (strided). Within a
//  tile each row appears once => race-free; tiles barrier-ordered =>
//  deterministic accumulation. Epilogue: cosine vs memories.
// ---------------------------------------------------------------------------
__global__ __launch_bounds__(256, 3) void attn_pass2(float* __restrict__ out)
{
  __shared__ float Ks[32*33];             // staged K tile [key][m], padded
  __shared__ float Vs[32*33];             // staged V tile
  __shared__ float accS[128*32];
  __shared__ float lS[128];
  __shared__ float Rm[128];
  __shared__ int   cnt[64];
  __shared__ unsigned char list[64*128];  // survivor rows per tile

  int tid = threadIdx.x, w = tid >> 5, lane = tid & 31;
  int eb = blockIdx.y, e = eb / B_, b = eb % B_;
  size_t ebT = (size_t)eb * T_;
  int qbase = blockIdx.x * 128;

  const float* Kg = g_K + ebT*M_;
  const float* Vg = g_V + ebT*M_;
  const float* Qg = g_Q + (ebT + qbase)*M_;

  // init + phase A: survivor lists
  for (int i = tid; i < 128*32; i += 256) accS[i] = 0.f;
  if (tid < 128){ Rm[tid] = g_Rmax[ebT + qbase + tid]; lS[tid] = 0.f; }
  if (tid < 64) cnt[tid] = 0;
  __syncthreads();
  {
    const __half* Tg = g_Tmaxh + (ebT + qbase)*64;
    #pragma unroll
    for (int j = 0; j < 32; j++){
      int p  = tid + j*256;               // p = row*64 + kt
      int row = p >> 6, kt = p & 63;
      if (__half2float(Tg[p]) >= Rm[row] - THR_){
        int slot = atomicAdd(&cnt[kt], 1);
        list[kt*128 + slot] = (unsigned char)row;
      }
    }
  }

  // prefetch tile 0: ONE tile = 32 keys * 32 f32 = 1024 elems = 4 * 256
  float pfk[4], pfv[4];
  #pragma unroll
  for (int j = 0; j < 4; j++){
    pfk[j] = __ldg(&Kg[tid + j*256]);
    pfv[j] = __ldg(&Vg[tid + j*256]);
  }

  for (int kt = 0; kt < 64; kt++){
    __syncthreads();                       // Ks/Vs free; also fences phase A
    #pragma unroll
    for (int j = 0; j < 4; j++){
      int i = tid + j*256;                 // key = i>>5 (0..31), m = i&31
      Ks[(i >> 5)*33 + (i & 31)] = pfk[j];
      Vs[(i >> 5)*33 + (i & 31)] = pfv[j];
    }
    __syncthreads();                       // tile ready
    if (kt < 63){
      const float* Kn = Kg + (size_t)(kt+1)*1024;
      const float* Vn = Vg + (size_t)(kt+1)*1024;
      #pragma unroll
      for (int j = 0; j < 4; j++){
        pfk[j] = __ldg(&Kn[tid + j*256]);
        pfv[j] = __ldg(&Vn[tid + j*256]);
      }
    }

    int n = cnt[kt];
    for (int v = w; v < n; v += 8){        // visits strided over warps
      int row = list[kt*128 + v];
      float q = Qg[(size_t)row*32 + lane]; // lane = m
      // scores: lane = key; 4 independent chains, shfl-broadcast q
      float s0 = 0.f, s1 = 0.f, s2 = 0.f, s3 = 0.f;
      #pragma unroll
      for (int m = 0; m < 8; m++){
        s0 = fmaf(__shfl_sync(0xffffffffu, q, m),      Ks[lane*33 + m],      s0);
        s1 = fmaf(__shfl_sync(0xffffffffu, q, m + 8),  Ks[lane*33 + m + 8],  s1);
        s2 = fmaf(__shfl_sync(0xffffffffu, q, m + 16), Ks[lane*33 + m + 16], s2);
        s3 = fmaf(__shfl_sync(0xffffffffu, q, m + 24), Ks[lane*33 + m + 24], s3);
      }
      float s = (s0 + s1) + (s2 + s3);
      float p = __expf(s - Rm[row]);       // shift cancels in acc/l exactly
      float sum = warpSum(p);
      // PV: lane = m; broadcast p from key lanes, 2 chains, V from smem
      float a0 = accS[row*32 + lane], a1 = 0.f;
      #pragma unroll
      for (int k = 0; k < 16; k++){
        a0 = fmaf(__shfl_sync(0xffffffffu, p, k),      Vs[k*33 + lane],        a0);
        a1 = fmaf(__shfl_sync(0xffffffffu, p, k + 16), Vs[(k + 16)*33 + lane], a1);
      }
      accS[row*32 + lane] = a0 + a1;
      if (lane == 0) lS[row] += sum;
    }
  }
  __syncthreads();

  // epilogue: cosine(out_row, memories[b,t]); warp owns 16 rows
  for (int r = 0; r < 16; r++){
    int row = w*16 + r, t = qbase + row;
    float o  = accS[row*32 + lane] / lS[row];
    float mv = g_mem[((size_t)b*T_ + t)*M_ + lane];
    float d  = warpSum(o*mv);
    float n1 = warpSum(o*o);
    float n2 = warpSum(mv*mv);
    if (lane == 0)
      out[((size_t)b*T_ + t)*E_ + e] =
          d / (fmaxf(sqrtf(n1), EPS_) * fmaxf(sqrtf(n2), EPS_));
  }
}

// ---------------------------------------------------------------------------
extern "C" void kernel_launch(void* const* d_in, const int* in_sizes, int n_in,
                              void* d_out, int out_size)
{
  const float* x      = (const float*)d_in[0];
  const float* hidden = (const float*)d_in[1];
  const float* memory = (const float*)d_in[2];
  const float* Wq     = (const float*)d_in[3];
  const float* Wk     = (const float*)d_in[4];
  const float* Wv     = (const float*)d_in[5];
  const float* iq     = (const float*)d_in[6];
  float* out = (float*)d_out;

  mem_kernel<<<B_*T_/4, 128>>>(x, memory, iq);
  qkv_kernel<<<dim3(B_*T_/64, E_), 256>>>(hidden, Wq, Wk, Wv);
  attn_pass1<<<dim3(T_/128, E_*B_), 256>>>();
  attn_pass2<<<dim3(T_/128, E_*B_), 256>>>(out);
}

// round 13
// speedup vs baseline: 5.2404x; 1.0261x over previous
#include <cuda_runtime.h>
#include <cuda_bf16.h>
#include <cuda_fp16.h>
#include <math.h>

#define B_ 8
#define T_ 2048
#define H_ 64
#define M_ 32
#define S_ 20
#define E_ 3
#define IN_ 32
#define EPS_ 1e-8f
#define THR_ 30.0f  // bf16 MMA err ~<3 + half Tmax err ~<1 << 30; dropped mass ~e^-26

// Scratch (allocation-free rule: __device__ globals)
__device__ float g_mem[B_*T_*M_];
__device__ float g_Q[E_*B_*T_*M_];
__device__ float g_K[E_*B_*T_*M_];
__device__ float g_V[E_*B_*T_*M_];
__device__ __nv_bfloat16 g_Qb[E_*B_*T_*M_];
__device__ __nv_bfloat16 g_Kb[E_*B_*T_*M_];
__device__ __half g_Tmaxh[E_*B_*T_*64];   // per-(row, key-tile) approx max
__device__ float g_Rmax[E_*B_*T_];        // per-row approx max

__device__ __forceinline__ float warpSum(float v){
  #pragma unroll
  for (int o=16;o>0;o>>=1) v += __shfl_xor_sync(0xffffffffu, v, o);
  return v;
}
__device__ __forceinline__ float warpMax(float v){
  #pragma unroll
  for (int o=16;o>0;o>>=1) v = fmaxf(v, __shfl_xor_sync(0xffffffffu, v, o));
  return v;
}

__device__ __forceinline__ void mma16816(float* c, const unsigned* a,
                                         unsigned b0, unsigned b1){
  asm volatile(
    "mma.sync.aligned.m16n8k16.row.col.f32.bf16.bf16.f32 "
    "{%0,%1,%2,%3}, {%4,%5,%6,%7}, {%8,%9}, {%0,%1,%2,%3};\n"
    : "+f"(c[0]), "+f"(c[1]), "+f"(c[2]), "+f"(c[3])
    : "r"(a[0]), "r"(a[1]), "r"(a[2]), "r"(a[3]), "r"(b0), "r"(b1));
}

// ---------------------------------------------------------------------------
// Kernel 1: memories = softmax(x@IQ @ memory^T) @ memory   per (b,t)
// ---------------------------------------------------------------------------
__global__ void mem_kernel(const float* __restrict__ x,
                           const float* __restrict__ memory,
                           const float* __restrict__ iq)
{
  __shared__ float IQs[IN_*M_];
  __shared__ float MEMT[33*33];
  int tid = threadIdx.x;
  for (int i = tid; i < IN_*M_; i += 128) IQs[i] = iq[i];
  for (int i = tid; i < 33*33;  i += 128){
    int s = i / 33, m = i % 33;
    MEMT[i] = (s < S_ && m < M_) ? memory[s*M_ + m] : 0.f;
  }
  __syncthreads();

  int warp = tid >> 5, lane = tid & 31;
  int bt = blockIdx.x*4 + warp;

  // q[m], lane = m
  float xv = x[bt*IN_ + lane];
  float q = 0.f;
  #pragma unroll
  for (int i = 0; i < IN_; i++)
    q += __shfl_sync(0xffffffffu, xv, i) * IQs[i*M_ + lane];

  // scores, lane = s (lanes >= 20 masked; padded MEMT rows are zero)
  float sc = 0.f;
  #pragma unroll
  for (int m = 0; m < M_; m++)
    sc = fmaf(__shfl_sync(0xffffffffu, q, m), MEMT[lane*33 + m], sc);
  float mx = warpMax(lane < S_ ? sc : -INFINITY);
  float p  = (lane < S_) ? __expf(sc - mx) : 0.f;
  float sum = warpSum(p);

  // memories[m], lane = m
  float mval = 0.f;
  #pragma unroll
  for (int s = 0; s < S_; s++)
    mval = fmaf(__shfl_sync(0xffffffffu, p, s), MEMT[s*33 + lane], mval);
  g_mem[bt*M_ + lane] = mval / sum;
}

// ---------------------------------------------------------------------------
// Kernel 2: Q/K/V projections; also emit bf16 copies of Q,K for pass-1 MMA.
// ---------------------------------------------------------------------------
__global__ __launch_bounds__(256) void qkv_kernel(const float* __restrict__ hidden,
                           const float* __restrict__ Wq,
                           const float* __restrict__ Wk,
                           const float* __restrict__ Wv)
{
  __shared__ float Wqs[H_*M_], Wks[H_*M_], Wvs[H_*M_];
  int e = blockIdx.y;
  int tid = threadIdx.x;
  for (int i = tid; i < H_*M_; i += 256){
    Wqs[i] = Wq[e*H_*M_ + i];
    Wks[i] = Wk[e*H_*M_ + i];
    Wvs[i] = Wv[e*H_*M_ + i];
  }
  __syncthreads();

  int warp = tid >> 5, lane = tid & 31;
  int rowBase = blockIdx.x*64 + warp*8;
  #pragma unroll
  for (int rr = 0; rr < 8; rr++){
    int row = rowBase + rr;
    long gr = (long)e*B_*T_ + row;
    float h0 = hidden[gr*H_ + lane];
    float h1 = hidden[gr*H_ + 32 + lane];
    float q = 0.f, k = 0.f, v = 0.f;
    #pragma unroll
    for (int h = 0; h < 32; h++){
      float hv = __shfl_sync(0xffffffffu, h0, h);
      q += hv*Wqs[h*M_+lane]; k += hv*Wks[h*M_+lane]; v += hv*Wvs[h*M_+lane];
    }
    #pragma unroll
    for (int h = 0; h < 32; h++){
      float hv = __shfl_sync(0xffffffffu, h1, h);
      q += hv*Wqs[(h+32)*M_+lane]; k += hv*Wks[(h+32)*M_+lane]; v += hv*Wvs[(h+32)*M_+lane];
    }
    g_Q[gr*M_+lane] = q; g_K[gr*M_+lane] = k; g_V[gr*M_+lane] = v;
    g_Qb[gr*M_+lane] = __float2bfloat16(q);
    g_Kb[gr*M_+lane] = __float2bfloat16(k);
  }
}

// ---------------------------------------------------------------------------
// Kernel 3a: pass 1 (bf16 HMMA) — per-(row, 32-key-tile) max + per-row max.
// ---------------------------------------------------------------------------
__global__ __launch_bounds__(256) void attn_pass1()
{
  __shared__ char KstRaw[10240];          // 128 keys x 40 bf16 (80B rows)
  __shared__ __half Tmx[128*64];          // [row][tile] 16KB

  int tid = threadIdx.x, w = tid >> 5, lane = tid & 31;
  int gid = lane >> 2, tig = lane & 3;
  int eb = blockIdx.y;
  size_t ebT = (size_t)eb * T_;
  int qbase = blockIdx.x * 128;
  int row_lo = qbase + w*16 + gid, row_hi = row_lo + 8;

  unsigned a[8];
  {
    const __nv_bfloat16* q0 = g_Qb + (ebT + row_lo)*M_;
    const __nv_bfloat16* q1 = g_Qb + (ebT + row_hi)*M_;
    a[0]=*(const unsigned*)(q0+2*tig);    a[1]=*(const unsigned*)(q1+2*tig);
    a[2]=*(const unsigned*)(q0+2*tig+8);  a[3]=*(const unsigned*)(q1+2*tig+8);
    a[4]=*(const unsigned*)(q0+2*tig+16); a[5]=*(const unsigned*)(q1+2*tig+16);
    a[6]=*(const unsigned*)(q0+2*tig+24); a[7]=*(const unsigned*)(q1+2*tig+24);
  }

  float mlo = -INFINITY, mhi = -INFINITY;

  const unsigned* Kbg = (const unsigned*)(g_Kb + ebT*M_);
  unsigned pf[8];
  #pragma unroll
  for (int i = 0; i < 8; i++) pf[i] = Kbg[tid + i*256];

  for (int c = 0; c < 16; c++){
    __syncthreads();
    #pragma unroll
    for (int i = 0; i < 8; i++){
      int lidx = tid + i*256;
      *(unsigned*)(KstRaw + (lidx >> 4)*80 + (lidx & 15)*4) = pf[i];
    }
    __syncthreads();
    if (c < 15){
      #pragma unroll
      for (int i = 0; i < 8; i++) pf[i] = Kbg[(c+1)*2048 + tid + i*256];
    }

    #pragma unroll
    for (int t = 0; t < 4; t++){
      int kt = c*4 + t;
      float tlo = -INFINITY, thi = -INFINITY;
      #pragma unroll
      for (int nb = 0; nb < 4; nb++){
        const char* bp = KstRaw + (t*32 + nb*8 + gid)*80 + tig*4;
        unsigned b0 = *(const unsigned*)(bp);
        unsigned b1 = *(const unsigned*)(bp + 16);
        unsigned b2 = *(const unsigned*)(bp + 32);
        unsigned b3 = *(const unsigned*)(bp + 48);
        float cc[4] = {0.f, 0.f, 0.f, 0.f};
        mma16816(cc, a,   b0, b1);
        mma16816(cc, a+4, b2, b3);
        tlo = fmaxf(tlo, fmaxf(cc[0], cc[1]));
        thi = fmaxf(thi, fmaxf(cc[2], cc[3]));
      }
      tlo = fmaxf(tlo, __shfl_xor_sync(0xffffffffu, tlo, 1));
      tlo = fmaxf(tlo, __shfl_xor_sync(0xffffffffu, tlo, 2));
      thi = fmaxf(thi, __shfl_xor_sync(0xffffffffu, thi, 1));
      thi = fmaxf(thi, __shfl_xor_sync(0xffffffffu, thi, 2));
      if (tig == 0){
        Tmx[(w*16 + gid)*64 + kt]     = __float2half_rn(tlo);
        Tmx[(w*16 + gid + 8)*64 + kt] = __float2half_rn(thi);
      }
      mlo = fmaxf(mlo, tlo); mhi = fmaxf(mhi, thi);
    }
  }
  if (tig == 0){
    g_Rmax[ebT + qbase + w*16 + gid]     = mlo;
    g_Rmax[ebT + qbase + w*16 + gid + 8] = mhi;
  }
  __syncthreads();
  unsigned* dst = (unsigned*)(g_Tmaxh + (ebT + qbase)*64);
  const unsigned* src = (const unsigned*)Tmx;
  for (int i = tid; i < 4096; i += 256) dst[i] = src[i];
}

// ---------------------------------------------------------------------------
// Kernel 3b: pass 2 — 4 key-tiles staged per iteration (16 iters, 32
// barriers). Visits assigned by row&7 == warp (race-free, deterministic:
// tiles processed in ascending order per warp). Per-tile survivor lists
// from phase A. Visit: 4 FMA score chains (shfl-broadcast q), one exp per
// 32 keys, PV from smem into accS. Epilogue: cosine vs memories.
// dynamic smem (floats):
//  Kbuf [4][32][33]=4224 | Vbuf 4224 | accS 4096 | lS 128 | Rm 128 |
//  cnt 64 int | list 64x64 u8 (1024 fl)   => 13888 floats = 55552 B
// ---------------------------------------------------------------------------
#define P2_SMEM_ 55552

__global__ __launch_bounds__(256, 3) void attn_pass2(float* __restrict__ out)
{
  extern __shared__ char sm2[];
  float* Kbuf = (float*)sm2;                   // [4][32][33]
  float* Vbuf = Kbuf + 4224;                   // [4][32][33]
  float* accS = Vbuf + 4224;                   // [128][32]
  float* lS   = accS + 4096;                   // [128]
  float* Rm   = lS + 128;                      // [128]
  int*   cnt  = (int*)(Rm + 128);              // [64]
  unsigned char* list = (unsigned char*)(cnt + 64);  // [64][64]

  int tid = threadIdx.x, w = tid >> 5, lane = tid & 31;
  int eb = blockIdx.y, e = eb / B_, b = eb % B_;
  size_t ebT = (size_t)eb * T_;
  int qbase = blockIdx.x * 128;

  const float* Kg = g_K + ebT*M_;
  const float* Vg = g_V + ebT*M_;
  const float* Qg = g_Q + (ebT + qbase)*M_;

  // init + phase A: per-tile survivor lists
  for (int i = tid; i < 128*32; i += 256) accS[i] = 0.f;
  if (tid < 128){ Rm[tid] = g_Rmax[ebT + qbase + tid]; lS[tid] = 0.f; }
  if (tid < 64) cnt[tid] = 0;
  __syncthreads();
  {
    const __half* Tg = g_Tmaxh + (ebT + qbase)*64;
    #pragma unroll
    for (int j = 0; j < 32; j++){
      int p  = tid + j*256;               // p = row*64 + kt
      int row = p >> 6, kt = p & 63;
      if (__half2float(Tg[p]) >= Rm[row] - THR_){
        int slot = atomicAdd(&cnt[kt], 1);
        if (slot < 64) list[kt*64 + slot] = (unsigned char)row;
      }
    }
  }

  // main loop: 16 groups of 4 tiles
  for (int g = 0; g < 16; g++){
    __syncthreads();                       // Kbuf/Vbuf free; fences phase A
    const float* Kgrp = Kg + (size_t)g*4096;   // 128 keys x 32 f32
    const float* Vgrp = Vg + (size_t)g*4096;
    #pragma unroll
    for (int j = 0; j < 4; j++){
      int f = tid + j*256;                 // float4 index: key = f>>3, m0=(f&7)*4
      float4 kv = __ldg((const float4*)(Kgrp + (size_t)f*4));
      float4 vv = __ldg((const float4*)(Vgrp + (size_t)f*4));
      int key = f >> 3, m0 = (f & 7)*4;
      float* kd = Kbuf + (key >> 5)*1056 + (key & 31)*33 + m0;
      float* vd = Vbuf + (key >> 5)*1056 + (key & 31)*33 + m0;
      kd[0]=kv.x; kd[1]=kv.y; kd[2]=kv.z; kd[3]=kv.w;
      vd[0]=vv.x; vd[1]=vv.y; vd[2]=vv.z; vd[3]=vv.w;
    }
    __syncthreads();                       // tiles ready

    #pragma unroll 1
    for (int t = 0; t < 4; t++){           // ascending tile order (determinism)
      int kt = g*4 + t;
      int n = min(cnt[kt], 64);
      const float* Kt = Kbuf + t*1056;
      const float* Vt = Vbuf + t*1056;
      #pragma unroll 1
      for (int v = 0; v < n; v++){
        int row = list[kt*64 + v];
        if ((row & 7) != w) continue;      // warp owns rows ≡ w (mod 8)
        float q = Qg[(size_t)row*32 + lane];   // lane = m
        // scores: lane = key; 4 independent chains, shfl-broadcast q
        float s0 = 0.f, s1 = 0.f, s2 = 0.f, s3 = 0.f;
        #pragma unroll
        for (int m = 0; m < 8; m++){
          s0 = fmaf(__shfl_sync(0xffffffffu, q, m),      Kt[lane*33 + m],      s0);
          s1 = fmaf(__shfl_sync(0xffffffffu, q, m + 8),  Kt[lane*33 + m + 8],  s1);
          s2 = fmaf(__shfl_sync(0xffffffffu, q, m + 16), Kt[lane*33 + m + 16], s2);
          s3 = fmaf(__shfl_sync(0xffffffffu, q, m + 24), Kt[lane*33 + m + 24], s3);
        }
        float s = (s0 + s1) + (s2 + s3);
        float p = __expf(s - Rm[row]);     // shift cancels in acc/l exactly
        float sum = warpSum(p);
        // PV: lane = m; broadcast p from key lanes, 2 chains
        float a0 = accS[row*32 + lane], a1 = 0.f;
        #pragma unroll
        for (int k = 0; k < 16; k++){
          a0 = fmaf(__shfl_sync(0xffffffffu, p, k),      Vt[k*33 + lane],        a0);
          a1 = fmaf(__shfl_sync(0xffffffffu, p, k + 16), Vt[(k + 16)*33 + lane], a1);
        }
        accS[row*32 + lane] = a0 + a1;
        if (lane == 0) lS[row] += sum;
      }
    }
  }
  __syncthreads();

  // epilogue: cosine(out_row, memories[b,t]); warp owns 16 rows
  for (int r = 0; r < 16; r++){
    int row = w*16 + r, t = qbase + row;
    float o  = accS[row*32 + lane] / lS[row];
    float mv = g_mem[((size_t)b*T_ + t)*M_ + lane];
    float d  = warpSum(o*mv);
    float n1 = warpSum(o*o);
    float n2 = warpSum(mv*mv);
    if (lane == 0)
      out[((size_t)b*T_ + t)*E_ + e] =
          d / (fmaxf(sqrtf(n1), EPS_) * fmaxf(sqrtf(n2), EPS_));
  }
}

// ---------------------------------------------------------------------------
extern "C" void kernel_launch(void* const* d_in, const int* in_sizes, int n_in,
                              void* d_out, int out_size)
{
  const float* x      = (const float*)d_in[0];
  const float* hidden = (const float*)d_in[1];
  const float* memory = (const float*)d_in[2];
  const float* Wq     = (const float*)d_in[3];
  const float* Wk     = (const float*)d_in[4];
  const float* Wv     = (const float*)d_in[5];
  const float* iq     = (const float*)d_in[6];
  float* out = (float*)d_out;

  cudaFuncSetAttribute(attn_pass2, cudaFuncAttributeMaxDynamicSharedMemorySize,
                       P2_SMEM_);

  mem_kernel<<<B_*T_/4, 128>>>(x, memory, iq);
  qkv_kernel<<<dim3(B_*T_/64, E_), 256>>>(hidden, Wq, Wk, Wv);
  attn_pass1<<<dim3(T_/128, E_*B_), 256>>>();
  attn_pass2<<<dim3(T_/128, E_*B_), 256, P2_SMEM_>>>(out);
}